// round 16
// baseline (speedup 1.0000x reference)
#include <cuda_runtime.h>
#include <math.h>

// ---------------- problem constants (fixed by reference setup_inputs) -------
#define B_    4
#define N_    4096
#define KN    32
#define NK    131072          // N_*KN
#define ROWS  524288          // B_*NK   (total point-neighbor rows)
#define CIN   64
#define COUT  64
#define M_    8
#define C1    16              // ScoreNet hidden channels
#define CNTF  524288.0f       // BN reduction count (B*N*k)
#define EPSF  1e-5f

// ---------------- device scratch (no allocations allowed) -------------------
__device__ float g_y_sum[C1];
__device__ float g_y_sq [C1];
__device__ float g_w1p  [C1 * 4];   // BN1 folded into conv1 weights
__device__ float g_b1p  [C1];       // BN1 folded bias
__device__ float g_o_sum[COUT];
__device__ float g_o_sq [COUT];

// ---------------- kernel 0: zero accumulators --------------------------------
__global__ void zero_stats_kernel() {
    int t = threadIdx.x;
    if (t < C1)   { g_y_sum[t] = 0.f; g_y_sq[t] = 0.f; }
    if (t < COUT) { g_o_sum[t] = 0.f; g_o_sq[t] = 0.f; }
}

// ---------------- kernel 1: BN1 statistics over conv1 outputs ---------------
// y[o] = w1[o,:4] . [x,y,z,|xyz|] ; accumulate sum(y), sum(y^2) per channel.
__global__ void stats1_kernel(const float* __restrict__ gxyz,
                              const float* __restrict__ w1) {
    __shared__ float sw1[C1 * 4];
    __shared__ float part[2 * C1];
    const int tid = threadIdx.x;
    if (tid < C1 * 4) sw1[tid] = w1[tid];
    if (tid < 2 * C1) part[tid] = 0.f;
    __syncthreads();

    float s[C1], q[C1];
#pragma unroll
    for (int o = 0; o < C1; o++) { s[o] = 0.f; q[o] = 0.f; }

    const int stride = gridDim.x * blockDim.x;
    for (int r = blockIdx.x * blockDim.x + tid; r < ROWS; r += stride) {
        const int b   = r >> 17;          // / NK
        const int rem = r & (NK - 1);
        const float* base = gxyz + (size_t)b * 3 * NK + rem;
        const float x = base[0];
        const float y = base[NK];
        const float z = base[2 * NK];
        const float e = sqrtf(x * x + y * y + z * z);
#pragma unroll
        for (int o = 0; o < C1; o++) {
            float v = sw1[o*4+0]*x + sw1[o*4+1]*y + sw1[o*4+2]*z + sw1[o*4+3]*e;
            s[o] += v;
            q[o] += v * v;
        }
    }

    // warp reduce, then shared, then global atomics
#pragma unroll
    for (int o = 0; o < C1; o++) {
#pragma unroll
        for (int off = 16; off > 0; off >>= 1) {
            s[o] += __shfl_down_sync(0xffffffffu, s[o], off);
            q[o] += __shfl_down_sync(0xffffffffu, q[o], off);
        }
    }
    if ((tid & 31) == 0) {
#pragma unroll
        for (int o = 0; o < C1; o++) {
            atomicAdd(&part[o],      s[o]);
            atomicAdd(&part[C1 + o], q[o]);
        }
    }
    __syncthreads();
    if (tid < C1)            atomicAdd(&g_y_sum[tid],      part[tid]);
    else if (tid < 2 * C1)   atomicAdd(&g_y_sq[tid - C1],  part[tid]);
}

// ---------------- kernel 2: fold BN1 into conv1 ------------------------------
__global__ void finalize1_kernel(const float* __restrict__ w1,
                                 const float* __restrict__ g1,
                                 const float* __restrict__ b1) {
    int o = threadIdx.x;
    if (o < C1) {
        const float invc = 1.0f / CNTF;
        float mean = g_y_sum[o] * invc;
        float var  = g_y_sq[o] * invc - mean * mean;
        float sc   = g1[o] * rsqrtf(var + EPSF);
        g_b1p[o] = b1[o] - mean * sc;
#pragma unroll
        for (int c = 0; c < 4; c++) g_w1p[o * 4 + c] = w1[o * 4 + c] * sc;
    }
}

// ---------------- kernel 3: main fused kernel --------------------------------
// Per block: 256 rows.  GEMM (256 x 64) = A(256 x 512) @ WB'(512 x 64), where
// A[r, m*64+i] = score[r,m] * feat[r,i] is formed in registers.
// SMEM: full weightbank (128KB) + feature tile f[i][row] (64KB) + scores + red.
#define SM_WB   32768                 // floats: 64*512
#define SM_F    16384                 // floats: 64*256
#define SM_S    2048                  // floats: 8*256
#define SM_RED  128
#define SMEM_FLOATS (SM_WB + SM_F + SM_S + SM_RED)
#define SMEM_BYTES  (SMEM_FLOATS * 4)

__global__ void __launch_bounds__(256, 1)
paconv_main_kernel(const float* __restrict__ gxyz,
                   const float* __restrict__ feat,
                   const float* __restrict__ w2,
                   const float* __restrict__ b2,
                   const float* __restrict__ wb,
                   float* __restrict__ out) {
    extern __shared__ float sm[];
    float* sWB  = sm;                         // [i*512 + mc]
    float* sF   = sm + SM_WB;                 // [i*256 + row]
    float* sS   = sm + SM_WB + SM_F;          // [m*256 + row]
    float* sRed = sm + SM_WB + SM_F + SM_S;   // [0..63]=sum, [64..127]=sumsq

    const int tid  = threadIdx.x;
    const int row0 = blockIdx.x << 8;         // 256 rows per block
    const int b    = row0 >> 17;              // block never crosses batch
    const int rem0 = row0 & (NK - 1);

    // ---- load weightbank (contiguous 128KB) ----
    {
        const float4* src = (const float4*)wb;
        float4*       dst = (float4*)sWB;
#pragma unroll
        for (int t = 0; t < 32; t++) dst[tid + (t << 8)] = src[tid + (t << 8)];
    }
    // ---- load feature tile: sF[i][row] ----
    {
#pragma unroll
        for (int t = 0; t < 16; t++) {
            int idx = tid + (t << 8);          // 0..4095 float4 slots
            int i   = idx >> 6;
            int r4  = idx & 63;
            ((float4*)(sF + (i << 8)))[r4] =
                ((const float4*)(feat + (size_t)(b * CIN + i) * NK + rem0))[r4];
        }
    }
    // ---- ScoreNet for this thread's row ----
    {
        const int rem = rem0 + tid;
        const float* gb = gxyz + (size_t)b * 3 * NK + rem;
        const float x = gb[0];
        const float y = gb[NK];
        const float z = gb[2 * NK];
        const float e = sqrtf(x * x + y * y + z * z);
        float h[C1];
#pragma unroll
        for (int o = 0; o < C1; o++) {
            float v = g_w1p[o*4+0]*x + g_w1p[o*4+1]*y + g_w1p[o*4+2]*z +
                      g_w1p[o*4+3]*e + g_b1p[o];
            h[o] = fmaxf(v, 0.0f);
        }
        float s[M_];
        float mx = -1e30f;
#pragma unroll
        for (int m = 0; m < M_; m++) {
            float v = __ldg(&b2[m]);
#pragma unroll
            for (int o = 0; o < C1; o++) v += __ldg(&w2[m * C1 + o]) * h[o];
            s[m] = v;
            mx = fmaxf(mx, v);
        }
        float den = 1.0f;  // softmax_one: denom = 1 + sum exp
#pragma unroll
        for (int m = 0; m < M_; m++) { s[m] = expf(s[m] - mx); den += s[m]; }
        const float inv = 1.0f / den;
#pragma unroll
        for (int m = 0; m < M_; m++) sS[(m << 8) + tid] = s[m] * inv;
    }
    if (tid < 128) sRed[tid] = 0.f;
    __syncthreads();

    // ---- register-tiled GEMM: 8 rows x 8 cols per thread ----
    const int tc = tid & 7;    // col tile  (8 tiles of 8 -> 64 cols)
    const int tr = tid >> 3;   // row tile  (32 tiles of 8 -> 256 rows)

    float acc[8][8];
#pragma unroll
    for (int a = 0; a < 8; a++)
#pragma unroll
        for (int c = 0; c < 8; c++) acc[a][c] = 0.f;

    const float4* sFa  = (const float4*)(sF  + tr * 8);   // + i*64 (f4 units)
    const float4* sWBb = (const float4*)(sWB + tc * 8);   // + i*128 + m*16

#pragma unroll 1
    for (int m = 0; m < M_; m++) {
        const float4 sv0 = *(const float4*)(sS + (m << 8) + tr * 8);
        const float4 sv1 = *(const float4*)(sS + (m << 8) + tr * 8 + 4);
        const float sfr[8] = {sv0.x, sv0.y, sv0.z, sv0.w,
                              sv1.x, sv1.y, sv1.z, sv1.w};
#pragma unroll 8
        for (int i = 0; i < CIN; i++) {
            const float4 a0 = sFa[i * 64];
            const float4 a1 = sFa[i * 64 + 1];
            const float4 b0 = sWBb[i * 128 + m * 16];
            const float4 b1 = sWBb[i * 128 + m * 16 + 1];
            const float af[8] = {a0.x * sfr[0], a0.y * sfr[1],
                                 a0.z * sfr[2], a0.w * sfr[3],
                                 a1.x * sfr[4], a1.y * sfr[5],
                                 a1.z * sfr[6], a1.w * sfr[7]};
            const float bf[8] = {b0.x, b0.y, b0.z, b0.w,
                                 b1.x, b1.y, b1.z, b1.w};
#pragma unroll
            for (int ii = 0; ii < 8; ii++)
#pragma unroll
                for (int jj = 0; jj < 8; jj++)
                    acc[ii][jj] += af[ii] * bf[jj];
        }
    }

    // ---- BN2 partial statistics (per output channel) ----
#pragma unroll
    for (int jj = 0; jj < 8; jj++) {
        float ssum = 0.f, ssq = 0.f;
#pragma unroll
        for (int ii = 0; ii < 8; ii++) {
            float v = acc[ii][jj];
            ssum += v;
            ssq  += v * v;
        }
        const int c = tc * 8 + jj;
        atomicAdd(&sRed[c],      ssum);
        atomicAdd(&sRed[64 + c], ssq);
    }

    // ---- write pre-BN output (float4 pairs, 64B-contiguous per 4 lanes) ----
#pragma unroll
    for (int jj = 0; jj < 8; jj++) {
        const int c = tc * 8 + jj;
        float* po = out + (size_t)(b * COUT + c) * NK + rem0 + tr * 8;
        float4 v0 = make_float4(acc[0][jj], acc[1][jj], acc[2][jj], acc[3][jj]);
        float4 v1 = make_float4(acc[4][jj], acc[5][jj], acc[6][jj], acc[7][jj]);
        ((float4*)po)[0] = v0;
        ((float4*)po)[1] = v1;
    }

    __syncthreads();
    if (tid < 64) {
        atomicAdd(&g_o_sum[tid], sRed[tid]);
        atomicAdd(&g_o_sq[tid],  sRed[64 + tid]);
    }
}

// ---------------- kernel 4: in-place BN2 + ReLU ------------------------------
__global__ void bn_relu_apply_kernel(const float* __restrict__ g_out,
                                     const float* __restrict__ b_out,
                                     float* __restrict__ out) {
    const float invc = 1.0f / CNTF;
    const int total4 = (B_ * COUT * NK) / 4;   // 8388608 float4s
    const int stride = gridDim.x * blockDim.x;
    for (int i4 = blockIdx.x * blockDim.x + threadIdx.x; i4 < total4; i4 += stride) {
        const int c = (i4 >> 15) & 63;         // (i4*4 / NK) % COUT
        const float mean = g_o_sum[c] * invc;
        const float var  = g_o_sq[c] * invc - mean * mean;
        const float sc   = __ldg(&g_out[c]) * rsqrtf(var + EPSF);
        const float sh   = __ldg(&b_out[c]) - mean * sc;
        float4 v = ((float4*)out)[i4];
        v.x = fmaxf(fmaf(v.x, sc, sh), 0.f);
        v.y = fmaxf(fmaf(v.y, sc, sh), 0.f);
        v.z = fmaxf(fmaf(v.z, sc, sh), 0.f);
        v.w = fmaxf(fmaf(v.w, sc, sh), 0.f);
        ((float4*)out)[i4] = v;
    }
}

// ---------------- launch ------------------------------------------------------
extern "C" void kernel_launch(void* const* d_in, const int* in_sizes, int n_in,
                              void* d_out, int out_size) {
    (void)in_sizes; (void)n_in; (void)out_size;
    const float* gxyz  = (const float*)d_in[0];
    const float* feat  = (const float*)d_in[1];
    const float* w1    = (const float*)d_in[2];
    const float* g1    = (const float*)d_in[3];
    const float* b1    = (const float*)d_in[4];
    const float* w2    = (const float*)d_in[5];
    const float* b2    = (const float*)d_in[6];
    const float* wb    = (const float*)d_in[7];
    const float* g_out = (const float*)d_in[8];
    const float* b_out = (const float*)d_in[9];
    float* out = (float*)d_out;

    cudaFuncSetAttribute(paconv_main_kernel,
                         cudaFuncAttributeMaxDynamicSharedMemorySize, SMEM_BYTES);

    zero_stats_kernel<<<1, 64>>>();
    stats1_kernel<<<256, 256>>>(gxyz, w1);
    finalize1_kernel<<<1, C1>>>(w1, g1, b1);
    paconv_main_kernel<<<ROWS / 256, 256, SMEM_BYTES>>>(gxyz, feat, w2, b2, wb, out);
    bn_relu_apply_kernel<<<4096, 256>>>(g_out, b_out, out);
}

// round 17
// speedup vs baseline: 1.1065x; 1.1065x over previous
#include <cuda_runtime.h>
#include <math.h>

// ---------------- problem constants (fixed by reference setup_inputs) -------
#define B_    4
#define N_    4096
#define KN    32
#define NK    131072          // N_*KN
#define ROWS  524288          // B_*NK   (total point-neighbor rows)
#define CIN   64
#define COUT  64
#define M_    8
#define C1    16              // ScoreNet hidden channels
#define CNTF  524288.0f       // BN reduction count (B*N*k)
#define EPSF  1e-5f

// ---------------- device scratch (no allocations allowed) -------------------
__device__ float g_y_sum[C1];
__device__ float g_y_sq [C1];
__device__ float g_w1p  [C1 * 4];   // BN1 folded into conv1 weights
__device__ float g_b1p  [C1];       // BN1 folded bias
__device__ float g_o_sum[COUT];
__device__ float g_o_sq [COUT];

// ---------------- packed f32x2 helpers (Blackwell sm_103a) -------------------
__device__ __forceinline__ unsigned long long pack2(float x, float y) {
    unsigned long long r;
    asm("mov.b64 %0, {%1, %2};" : "=l"(r) : "f"(x), "f"(y));
    return r;
}
__device__ __forceinline__ void unpack2(unsigned long long v, float& x, float& y) {
    asm("mov.b64 {%0, %1}, %2;" : "=f"(x), "=f"(y) : "l"(v));
}
__device__ __forceinline__ unsigned long long fma2(unsigned long long a,
                                                   unsigned long long b,
                                                   unsigned long long c) {
    unsigned long long d;
    asm("fma.rn.f32x2 %0, %1, %2, %3;" : "=l"(d) : "l"(a), "l"(b), "l"(c));
    return d;
}
__device__ __forceinline__ unsigned long long mul2(unsigned long long a,
                                                   unsigned long long b) {
    unsigned long long d;
    asm("mul.rn.f32x2 %0, %1, %2;" : "=l"(d) : "l"(a), "l"(b));
    return d;
}

// ---------------- kernel 0: zero accumulators --------------------------------
__global__ void zero_stats_kernel() {
    int t = threadIdx.x;
    if (t < C1)   { g_y_sum[t] = 0.f; g_y_sq[t] = 0.f; }
    if (t < COUT) { g_o_sum[t] = 0.f; g_o_sq[t] = 0.f; }
}

// ---------------- kernel 1: BN1 statistics over conv1 outputs ---------------
__global__ void stats1_kernel(const float* __restrict__ gxyz,
                              const float* __restrict__ w1) {
    __shared__ float sw1[C1 * 4];
    __shared__ float part[2 * C1];
    const int tid = threadIdx.x;
    if (tid < C1 * 4) sw1[tid] = w1[tid];
    if (tid < 2 * C1) part[tid] = 0.f;
    __syncthreads();

    float s[C1], q[C1];
#pragma unroll
    for (int o = 0; o < C1; o++) { s[o] = 0.f; q[o] = 0.f; }

    const int stride = gridDim.x * blockDim.x;
    for (int r = blockIdx.x * blockDim.x + tid; r < ROWS; r += stride) {
        const int b   = r >> 17;
        const int rem = r & (NK - 1);
        const float* base = gxyz + (size_t)b * 3 * NK + rem;
        const float x = base[0];
        const float y = base[NK];
        const float z = base[2 * NK];
        const float e = sqrtf(x * x + y * y + z * z);
#pragma unroll
        for (int o = 0; o < C1; o++) {
            float v = sw1[o*4+0]*x + sw1[o*4+1]*y + sw1[o*4+2]*z + sw1[o*4+3]*e;
            s[o] += v;
            q[o] += v * v;
        }
    }

#pragma unroll
    for (int o = 0; o < C1; o++) {
#pragma unroll
        for (int off = 16; off > 0; off >>= 1) {
            s[o] += __shfl_down_sync(0xffffffffu, s[o], off);
            q[o] += __shfl_down_sync(0xffffffffu, q[o], off);
        }
    }
    if ((tid & 31) == 0) {
#pragma unroll
        for (int o = 0; o < C1; o++) {
            atomicAdd(&part[o],      s[o]);
            atomicAdd(&part[C1 + o], q[o]);
        }
    }
    __syncthreads();
    if (tid < C1)            atomicAdd(&g_y_sum[tid],      part[tid]);
    else if (tid < 2 * C1)   atomicAdd(&g_y_sq[tid - C1],  part[tid]);
}

// ---------------- kernel 2: fold BN1 into conv1 ------------------------------
__global__ void finalize1_kernel(const float* __restrict__ w1,
                                 const float* __restrict__ g1,
                                 const float* __restrict__ b1) {
    int o = threadIdx.x;
    if (o < C1) {
        const float invc = 1.0f / CNTF;
        float mean = g_y_sum[o] * invc;
        float var  = g_y_sq[o] * invc - mean * mean;
        float sc   = g1[o] * rsqrtf(var + EPSF);
        g_b1p[o] = b1[o] - mean * sc;
#pragma unroll
        for (int c = 0; c < 4; c++) g_w1p[o * 4 + c] = w1[o * 4 + c] * sc;
    }
}

// ---------------- kernel 3: main fused kernel --------------------------------
// Per block: 256 rows.  GEMM (256 x 64) = A(256 x 512) @ WB'(512 x 64), where
// A[r, m*64+i] = score[r,m] * feat[r,i] is formed in registers.
// Inner product executed with packed fma.rn.f32x2 (row-pairs x col).
#define SM_WB   32768                 // floats: 64*512
#define SM_F    16384                 // floats: 64*256
#define SM_S    2048                  // floats: 8*256
#define SM_RED  128
#define SMEM_FLOATS (SM_WB + SM_F + SM_S + SM_RED)
#define SMEM_BYTES  (SMEM_FLOATS * 4)

__global__ void __launch_bounds__(256, 1)
paconv_main_kernel(const float* __restrict__ gxyz,
                   const float* __restrict__ feat,
                   const float* __restrict__ w2,
                   const float* __restrict__ b2,
                   const float* __restrict__ wb,
                   float* __restrict__ out) {
    extern __shared__ float sm[];
    float* sWB  = sm;                         // [i*512 + mc]
    float* sF   = sm + SM_WB;                 // [i*256 + row]
    float* sS   = sm + SM_WB + SM_F;          // [m*256 + row]
    float* sRed = sm + SM_WB + SM_F + SM_S;   // [0..63]=sum, [64..127]=sumsq

    const int tid  = threadIdx.x;
    const int row0 = blockIdx.x << 8;         // 256 rows per block
    const int b    = row0 >> 17;              // block never crosses batch
    const int rem0 = row0 & (NK - 1);

    // ---- load weightbank (contiguous 128KB) ----
    {
        const float4* src = (const float4*)wb;
        float4*       dst = (float4*)sWB;
#pragma unroll
        for (int t = 0; t < 32; t++) dst[tid + (t << 8)] = src[tid + (t << 8)];
    }
    // ---- load feature tile: sF[i][row] ----
    {
#pragma unroll
        for (int t = 0; t < 16; t++) {
            int idx = tid + (t << 8);          // 0..4095 float4 slots
            int i   = idx >> 6;
            int r4  = idx & 63;
            ((float4*)(sF + (i << 8)))[r4] =
                ((const float4*)(feat + (size_t)(b * CIN + i) * NK + rem0))[r4];
        }
    }
    // ---- ScoreNet for this thread's row ----
    {
        const int rem = rem0 + tid;
        const float* gb = gxyz + (size_t)b * 3 * NK + rem;
        const float x = gb[0];
        const float y = gb[NK];
        const float z = gb[2 * NK];
        const float e = sqrtf(x * x + y * y + z * z);
        float h[C1];
#pragma unroll
        for (int o = 0; o < C1; o++) {
            float v = g_w1p[o*4+0]*x + g_w1p[o*4+1]*y + g_w1p[o*4+2]*z +
                      g_w1p[o*4+3]*e + g_b1p[o];
            h[o] = fmaxf(v, 0.0f);
        }
        float s[M_];
        float mx = -1e30f;
#pragma unroll
        for (int m = 0; m < M_; m++) {
            float v = __ldg(&b2[m]);
#pragma unroll
            for (int o = 0; o < C1; o++) v += __ldg(&w2[m * C1 + o]) * h[o];
            s[m] = v;
            mx = fmaxf(mx, v);
        }
        float den = 1.0f;  // softmax_one: denom = 1 + sum exp
#pragma unroll
        for (int m = 0; m < M_; m++) { s[m] = expf(s[m] - mx); den += s[m]; }
        const float inv = 1.0f / den;
#pragma unroll
        for (int m = 0; m < M_; m++) sS[(m << 8) + tid] = s[m] * inv;
    }
    if (tid < 128) sRed[tid] = 0.f;
    __syncthreads();

    // ---- register-tiled GEMM: 8 rows x 8 cols per thread, packed f32x2 ----
    // acc[p][jj] = { out[row 2p][jj], out[row 2p+1][jj] }
    const int tc = tid & 7;    // col tile  (8 tiles of 8 -> 64 cols)
    const int tr = tid >> 3;   // row tile  (32 tiles of 8 -> 256 rows)

    unsigned long long acc[4][8];
#pragma unroll
    for (int p = 0; p < 4; p++)
#pragma unroll
        for (int jj = 0; jj < 8; jj++) acc[p][jj] = 0ull;

    const float* sFa  = sF  + tr * 8;          // + i*256
    const float* sWBb = sWB + tc * 8;          // + i*512 + m*64

#pragma unroll 1
    for (int m = 0; m < M_; m++) {
        // packed score pairs for this thread's 8 rows (fixed over i)
        const ulonglong2 sv0 = *(const ulonglong2*)(sS + (m << 8) + tr * 8);
        const ulonglong2 sv1 = *(const ulonglong2*)(sS + (m << 8) + tr * 8 + 4);
        const unsigned long long sp[4] = {sv0.x, sv0.y, sv1.x, sv1.y};
#pragma unroll 8
        for (int i = 0; i < CIN; i++) {
            // feature row pairs (8 consecutive rows -> 4 packed pairs)
            const ulonglong2 a0 = *(const ulonglong2*)(sFa + i * 256);
            const ulonglong2 a1 = *(const ulonglong2*)(sFa + i * 256 + 4);
            // scale by score: af[p] = a_pair[p] * {s,s-pair}
            unsigned long long af[4];
            af[0] = mul2(a0.x, sp[0]);
            af[1] = mul2(a0.y, sp[1]);
            af[2] = mul2(a1.x, sp[2]);
            af[3] = mul2(a1.y, sp[3]);
            // weightbank column values (8 scalars), broadcast into pairs
            const float4 b0 = *(const float4*)(sWBb + i * 512 + (m << 6));
            const float4 b1 = *(const float4*)(sWBb + i * 512 + (m << 6) + 4);
            const float bf[8] = {b0.x, b0.y, b0.z, b0.w,
                                 b1.x, b1.y, b1.z, b1.w};
            unsigned long long bb[8];
#pragma unroll
            for (int jj = 0; jj < 8; jj++) bb[jj] = pack2(bf[jj], bf[jj]);
#pragma unroll
            for (int p = 0; p < 4; p++)
#pragma unroll
                for (int jj = 0; jj < 8; jj++)
                    acc[p][jj] = fma2(af[p], bb[jj], acc[p][jj]);
        }
    }

    // ---- unpack accumulators ----
    float accf[8][8];
#pragma unroll
    for (int p = 0; p < 4; p++)
#pragma unroll
        for (int jj = 0; jj < 8; jj++)
            unpack2(acc[p][jj], accf[2 * p][jj], accf[2 * p + 1][jj]);

    // ---- BN2 partial statistics (per output channel) ----
#pragma unroll
    for (int jj = 0; jj < 8; jj++) {
        float ssum = 0.f, ssq = 0.f;
#pragma unroll
        for (int ii = 0; ii < 8; ii++) {
            float v = accf[ii][jj];
            ssum += v;
            ssq  += v * v;
        }
        const int c = tc * 8 + jj;
        atomicAdd(&sRed[c],      ssum);
        atomicAdd(&sRed[64 + c], ssq);
    }

    // ---- write pre-BN output ----
#pragma unroll
    for (int jj = 0; jj < 8; jj++) {
        const int c = tc * 8 + jj;
        float* po = out + (size_t)(b * COUT + c) * NK + rem0 + tr * 8;
        float4 v0 = make_float4(accf[0][jj], accf[1][jj], accf[2][jj], accf[3][jj]);
        float4 v1 = make_float4(accf[4][jj], accf[5][jj], accf[6][jj], accf[7][jj]);
        ((float4*)po)[0] = v0;
        ((float4*)po)[1] = v1;
    }

    __syncthreads();
    if (tid < 64) {
        atomicAdd(&g_o_sum[tid], sRed[tid]);
        atomicAdd(&g_o_sq[tid],  sRed[64 + tid]);
    }
}

// ---------------- kernel 4: in-place BN2 + ReLU ------------------------------
__global__ void bn_relu_apply_kernel(const float* __restrict__ g_out,
                                     const float* __restrict__ b_out,
                                     float* __restrict__ out) {
    const float invc = 1.0f / CNTF;
    const int total4 = (B_ * COUT * NK) / 4;   // 8388608 float4s
    const int stride = gridDim.x * blockDim.x;
    for (int i4 = blockIdx.x * blockDim.x + threadIdx.x; i4 < total4; i4 += stride) {
        const int c = (i4 >> 15) & 63;         // (i4*4 / NK) % COUT
        const float mean = g_o_sum[c] * invc;
        const float var  = g_o_sq[c] * invc - mean * mean;
        const float sc   = __ldg(&g_out[c]) * rsqrtf(var + EPSF);
        const float sh   = __ldg(&b_out[c]) - mean * sc;
        float4 v = ((float4*)out)[i4];
        v.x = fmaxf(fmaf(v.x, sc, sh), 0.f);
        v.y = fmaxf(fmaf(v.y, sc, sh), 0.f);
        v.z = fmaxf(fmaf(v.z, sc, sh), 0.f);
        v.w = fmaxf(fmaf(v.w, sc, sh), 0.f);
        ((float4*)out)[i4] = v;
    }
}

// ---------------- launch ------------------------------------------------------
extern "C" void kernel_launch(void* const* d_in, const int* in_sizes, int n_in,
                              void* d_out, int out_size) {
    (void)in_sizes; (void)n_in; (void)out_size;
    const float* gxyz  = (const float*)d_in[0];
    const float* feat  = (const float*)d_in[1];
    const float* w1    = (const float*)d_in[2];
    const float* g1    = (const float*)d_in[3];
    const float* b1    = (const float*)d_in[4];
    const float* w2    = (const float*)d_in[5];
    const float* b2    = (const float*)d_in[6];
    const float* wb    = (const float*)d_in[7];
    const float* g_out = (const float*)d_in[8];
    const float* b_out = (const float*)d_in[9];
    float* out = (float*)d_out;

    cudaFuncSetAttribute(paconv_main_kernel,
                         cudaFuncAttributeMaxDynamicSharedMemorySize, SMEM_BYTES);

    zero_stats_kernel<<<1, 64>>>();
    stats1_kernel<<<256, 256>>>(gxyz, w1);
    finalize1_kernel<<<1, C1>>>(w1, g1, b1);
    paconv_main_kernel<<<ROWS / 256, 256, SMEM_BYTES>>>(gxyz, feat, w2, b2, wb, out);
    bn_relu_apply_kernel<<<4096, 256>>>(g_out, b_out, out);
}